// round 2
// baseline (speedup 1.0000x reference)
#include <cuda_runtime.h>
#include <cuda_bf16.h>
#include <math.h>

#define NN 50000
#define FIN 128
#define F1 256
#define HH 8
#define CH 32
#define NC 40
#define EMAX 1000000

// ---------------- scratch (device globals; no allocation allowed) -----------
__device__ float g_h1[NN * F1];          // layer1 features per node
__device__ float g_h2[NN * F1];          // elu(aggregated + b1)
__device__ float g_as1[NN * HH];
__device__ float g_ad1[NN * HH];
__device__ float g_g[NN * NC];           // layer2 per-node features
__device__ float g_a2s[NN];
__device__ float g_a2d[NN];
__device__ int   g_deg[NN];
__device__ int   g_rowptr[NN + 1];
__device__ int   g_cursor[NN + 1];
__device__ int   g_csrsrc[EMAX];
__device__ int   g_part[64];
__device__ int   g_is64;

// ---------------- helpers ---------------------------------------------------
__device__ __forceinline__ int edge_at(const void* p, long long i, int is64) {
    if (is64) return (int)((const long long*)p)[i];
    return ((const int*)p)[i];
}
__device__ __forceinline__ float lrelu(float v) { return v > 0.f ? v : 0.2f * v; }

// ---------------- dtype detection ------------------------------------------
__global__ void k_detect(const void* ei, int n) {
    int bad = 0;
    for (int i = threadIdx.x; i < 1024; i += blockDim.x) {
        long long v = ((const long long*)ei)[i];
        if (v < 0 || v >= n) bad = 1;
    }
    int anybad = __syncthreads_or(bad);
    if (threadIdx.x == 0) g_is64 = anybad ? 0 : 1;
}

// ---------------- GEMM1: h1 = x @ W1  (NxFIN @ FINxF1) ----------------------
__global__ void k_gemm1(const float* __restrict__ x, const float* __restrict__ W1, int n) {
    const int BM = 128, BN = 128, BK = 8;
    __shared__ float As[BK][BM];
    __shared__ float Bs[BK][BN];
    int t = threadIdx.x;
    int tx = t % 16, ty = t / 16;
    int bm0 = blockIdx.x * BM, bn0 = blockIdx.y * BN;
    float acc[8][8];
#pragma unroll
    for (int i = 0; i < 8; i++)
#pragma unroll
        for (int j = 0; j < 8; j++) acc[i][j] = 0.f;

    int ar = t >> 1, ac4 = (t & 1) * 4;
    int br = t >> 5, bc4 = (t & 31) * 4;

    for (int kk = 0; kk < FIN; kk += BK) {
        float4 av = make_float4(0.f, 0.f, 0.f, 0.f);
        if (bm0 + ar < n)
            av = *(const float4*)&x[(long long)(bm0 + ar) * FIN + kk + ac4];
        As[ac4 + 0][ar] = av.x;
        As[ac4 + 1][ar] = av.y;
        As[ac4 + 2][ar] = av.z;
        As[ac4 + 3][ar] = av.w;
        float4 bv = *(const float4*)&W1[(long long)(kk + br) * F1 + bn0 + bc4];
        *(float4*)&Bs[br][bc4] = bv;
        __syncthreads();
#pragma unroll
        for (int k = 0; k < BK; k++) {
            float a[8], b[8];
            *(float4*)&a[0] = *(float4*)&As[k][ty * 8];
            *(float4*)&a[4] = *(float4*)&As[k][ty * 8 + 4];
            *(float4*)&b[0] = *(float4*)&Bs[k][tx * 8];
            *(float4*)&b[4] = *(float4*)&Bs[k][tx * 8 + 4];
#pragma unroll
            for (int i = 0; i < 8; i++)
#pragma unroll
                for (int j = 0; j < 8; j++) acc[i][j] += a[i] * b[j];
        }
        __syncthreads();
    }
#pragma unroll
    for (int i = 0; i < 8; i++) {
        int row = bm0 + ty * 8 + i;
        if (row < n) {
            *(float4*)&g_h1[(long long)row * F1 + bn0 + tx * 8]     = *(float4*)&acc[i][0];
            *(float4*)&g_h1[(long long)row * F1 + bn0 + tx * 8 + 4] = *(float4*)&acc[i][4];
        }
    }
}

// ---------------- attention prep layer1: as1/ad1 ----------------------------
__global__ void k_attprep1(const float* __restrict__ a1src, const float* __restrict__ a1dst, int n) {
    __shared__ float s1[F1], s2[F1];
    int t = threadIdx.x;
    s1[t] = a1src[t];
    s2[t] = a1dst[t];
    __syncthreads();
    int nd = blockIdx.x * 8 + (t >> 5);
    int lane = t & 31;
    if (nd >= n) return;
#pragma unroll
    for (int h = 0; h < HH; h++) {
        int idx = h * 32 + lane;
        float v = g_h1[(long long)nd * F1 + idx];
        float ps = v * s1[idx];
        float pd = v * s2[idx];
#pragma unroll
        for (int off = 16; off > 0; off >>= 1) {
            ps += __shfl_xor_sync(0xffffffff, ps, off);
            pd += __shfl_xor_sync(0xffffffff, pd, off);
        }
        if (lane == 0) {
            g_as1[nd * HH + h] = ps;
            g_ad1[nd * HH + h] = pd;
        }
    }
}

// ---------------- CSR construction ------------------------------------------
__global__ void k_deginit(int n) {
    int i = blockIdx.x * blockDim.x + threadIdx.x;
    if (i < n) g_deg[i] = 1;  // self-loop
}
__global__ void k_hist(const void* ei, int E) {
    int is64 = g_is64;
    for (int i = blockIdx.x * blockDim.x + threadIdx.x; i < E; i += gridDim.x * blockDim.x) {
        int d = edge_at(ei, (long long)E + i, is64);
        atomicAdd(&g_deg[d], 1);
    }
}
__global__ void k_scan1(int n) {
    __shared__ int ssum[256];
    int b = blockIdx.x, t = threadIdx.x;
    int base = b * 1024 + t * 4;
    int v[4];
    int tsum = 0;
#pragma unroll
    for (int j = 0; j < 4; j++) {
        int idx = base + j;
        v[j] = (idx < n) ? g_deg[idx] : 0;
        tsum += v[j];
    }
    ssum[t] = tsum;
    __syncthreads();
    for (int off = 1; off < 256; off <<= 1) {
        int x = (t >= off) ? ssum[t - off] : 0;
        __syncthreads();
        ssum[t] += x;
        __syncthreads();
    }
    int run = ssum[t] - tsum;
#pragma unroll
    for (int j = 0; j < 4; j++) {
        run += v[j];
        if (base + j < n) g_rowptr[base + j + 1] = run;
    }
    if (t == 255) g_part[b] = ssum[255];
}
__global__ void k_scan2(int nb) {
    if (threadIdx.x == 0 && blockIdx.x == 0) {
        int run = 0;
        for (int b = 0; b < nb; b++) {
            int t = g_part[b];
            g_part[b] = run;
            run += t;
        }
        g_rowptr[0] = 0;
        g_cursor[0] = 0;
    }
}
__global__ void k_scan3(int n) {
    int b = blockIdx.x, t = threadIdx.x;
    int off = g_part[b];
    int base = b * 1024 + t * 4;
#pragma unroll
    for (int j = 0; j < 4; j++) {
        int idx = base + j;
        if (idx < n) {
            int v = g_rowptr[idx + 1] + off;
            g_rowptr[idx + 1] = v;
            g_cursor[idx + 1] = v;
        }
    }
}
__global__ void k_fill(const void* ei, int E, int n) {
    int is64 = g_is64;
    int total = E + n;
    for (int i = blockIdx.x * blockDim.x + threadIdx.x; i < total; i += gridDim.x * blockDim.x) {
        int s, d;
        if (i < E) {
            s = edge_at(ei, i, is64);
            d = edge_at(ei, (long long)E + i, is64);
        } else {
            s = d = i - E;
        }
        int p = atomicAdd(&g_cursor[d], 1);
        g_csrsrc[p] = s;
    }
}

// ---------------- layer1 edge softmax + aggregate + bias + elu --------------
__global__ void k_agg1(const float* __restrict__ b1) {
    int n = blockIdx.x;
    int tid = threadIdx.x;
    __shared__ float ad[HH], fm[HH], inv[HH];
    __shared__ float red[8][HH];
    __shared__ float b1s[F1];
    __shared__ int src_s[64];
    __shared__ float w_s[64][HH];
    __shared__ float4 accbuf[4][64];

    int beg = g_rowptr[n], end = g_rowptr[n + 1];
    int deg = end - beg;
    if (tid < HH) ad[tid] = g_ad1[n * HH + tid];
    b1s[tid] = b1[tid];
    __syncthreads();

    int wid = tid >> 5, lane = tid & 31;

    // pass 1: per-head max
    float mx[HH];
#pragma unroll
    for (int h = 0; h < HH; h++) mx[h] = -1e30f;
    for (int i = tid; i < deg; i += 256) {
        int s = g_csrsrc[beg + i];
        const float* as = &g_as1[s * HH];
#pragma unroll
        for (int h = 0; h < HH; h++) {
            float v = lrelu(as[h] + ad[h]);
            mx[h] = fmaxf(mx[h], v);
        }
    }
#pragma unroll
    for (int h = 0; h < HH; h++) {
        float v = mx[h];
#pragma unroll
        for (int off = 16; off > 0; off >>= 1) v = fmaxf(v, __shfl_xor_sync(0xffffffff, v, off));
        if (lane == 0) red[wid][h] = v;
    }
    __syncthreads();
    if (tid < HH) {
        float m = -1e30f;
#pragma unroll
        for (int w = 0; w < 8; w++) m = fmaxf(m, red[w][tid]);
        fm[tid] = m;
    }
    __syncthreads();

    // pass 2: per-head sum(exp)
    float sm[HH];
#pragma unroll
    for (int h = 0; h < HH; h++) sm[h] = 0.f;
    for (int i = tid; i < deg; i += 256) {
        int s = g_csrsrc[beg + i];
        const float* as = &g_as1[s * HH];
#pragma unroll
        for (int h = 0; h < HH; h++) {
            float v = lrelu(as[h] + ad[h]);
            sm[h] += __expf(v - fm[h]);
        }
    }
#pragma unroll
    for (int h = 0; h < HH; h++) {
        float v = sm[h];
#pragma unroll
        for (int off = 16; off > 0; off >>= 1) v += __shfl_xor_sync(0xffffffff, v, off);
        if (lane == 0) red[wid][h] = v;
    }
    __syncthreads();
    if (tid < HH) {
        float s = 0.f;
#pragma unroll
        for (int w = 0; w < 8; w++) s += red[w][tid];
        inv[tid] = 1.f / (s + 1e-16f);
    }
    __syncthreads();

    // pass 3: weighted gather, float4 per thread, 4 edge-slots
    int f4 = tid & 63, slot = tid >> 6, h4 = f4 >> 3;
    float4 acc = make_float4(0.f, 0.f, 0.f, 0.f);
    const float4* h1v = (const float4*)g_h1;
    for (int base = 0; base < deg; base += 64) {
        int cnt = min(64, deg - base);
        __syncthreads();
        if (tid < cnt) src_s[tid] = g_csrsrc[beg + base + tid];
        __syncthreads();
        for (int job = tid; job < cnt * HH; job += 256) {
            int e = job >> 3, h = job & 7;
            int s = src_s[e];
            float v = lrelu(g_as1[s * HH + h] + ad[h]);
            w_s[e][h] = __expf(v - fm[h]) * inv[h];
        }
        __syncthreads();
        for (int e = slot; e < cnt; e += 4) {
            float w = w_s[e][h4];
            float4 hv = h1v[(long long)src_s[e] * 64 + f4];
            acc.x += w * hv.x;
            acc.y += w * hv.y;
            acc.z += w * hv.z;
            acc.w += w * hv.w;
        }
    }
    accbuf[slot][f4] = acc;
    __syncthreads();
    if (tid < 64) {
        float4 a = accbuf[0][tid];
#pragma unroll
        for (int s = 1; s < 4; s++) {
            float4 b = accbuf[s][tid];
            a.x += b.x; a.y += b.y; a.z += b.z; a.w += b.w;
        }
        int fb = tid * 4;
        float o0 = a.x + b1s[fb + 0];
        float o1 = a.y + b1s[fb + 1];
        float o2 = a.z + b1s[fb + 2];
        float o3 = a.w + b1s[fb + 3];
        float4 r;
        r.x = o0 > 0.f ? o0 : (__expf(o0) - 1.f);
        r.y = o1 > 0.f ? o1 : (__expf(o1) - 1.f);
        r.z = o2 > 0.f ? o2 : (__expf(o2) - 1.f);
        r.w = o3 > 0.f ? o3 : (__expf(o3) - 1.f);
        *(float4*)&g_h2[(long long)n * F1 + fb] = r;
    }
}

// ---------------- GEMM2: g = h2 @ W2  (NxF1 @ F1xNC) ------------------------
__global__ void k_gemm2(const float* __restrict__ W2, int n) {
    const int BM = 256, BK = 16;
    __shared__ float h2s[BM][BK + 1];
    __shared__ float W2s[BK * NC];
    int t = threadIdx.x;
    int rg = t >> 2;   // 0..63  -> 4 rows each
    int q = t & 3;     // 0..3   -> 10 cols each
    int bm0 = blockIdx.x * BM;
    float acc[4][10];
#pragma unroll
    for (int i = 0; i < 4; i++)
#pragma unroll
        for (int j = 0; j < 10; j++) acc[i][j] = 0.f;

    for (int kc = 0; kc < F1; kc += BK) {
#pragma unroll
        for (int j = 0; j < 4; j++) {
            int li = t + 256 * j;
            int row = li >> 2;
            int c4 = li & 3;
            float4 v = make_float4(0.f, 0.f, 0.f, 0.f);
            if (bm0 + row < n)
                v = *(const float4*)&g_h2[(long long)(bm0 + row) * F1 + kc + c4 * 4];
            h2s[row][c4 * 4 + 0] = v.x;
            h2s[row][c4 * 4 + 1] = v.y;
            h2s[row][c4 * 4 + 2] = v.z;
            h2s[row][c4 * 4 + 3] = v.w;
        }
        if (t < 160)
            *(float4*)&W2s[t * 4] = *(const float4*)&W2[kc * NC + t * 4];
        __syncthreads();
#pragma unroll
        for (int k = 0; k < BK; k++) {
            float a0 = h2s[rg * 4 + 0][k];
            float a1 = h2s[rg * 4 + 1][k];
            float a2 = h2s[rg * 4 + 2][k];
            float a3 = h2s[rg * 4 + 3][k];
#pragma unroll
            for (int j = 0; j < 10; j++) {
                float b = W2s[k * NC + q * 10 + j];
                acc[0][j] += a0 * b;
                acc[1][j] += a1 * b;
                acc[2][j] += a2 * b;
                acc[3][j] += a3 * b;
            }
        }
        __syncthreads();
    }
#pragma unroll
    for (int i = 0; i < 4; i++) {
        int row = bm0 + rg * 4 + i;
        if (row < n) {
#pragma unroll
            for (int j = 0; j < 10; j++) g_g[(long long)row * NC + q * 10 + j] = acc[i][j];
        }
    }
}

// ---------------- attention prep layer2 -------------------------------------
__global__ void k_attprep2(const float* __restrict__ a2src, const float* __restrict__ a2dst, int n) {
    __shared__ float s1[NC], s2[NC];
    int t = threadIdx.x;
    if (t < NC) {
        s1[t] = a2src[t];
        s2[t] = a2dst[t];
    }
    __syncthreads();
    int nd = blockIdx.x * 8 + (t >> 5);
    int lane = t & 31;
    if (nd >= n) return;
    float ps = 0.f, pd = 0.f;
    for (int c = lane; c < NC; c += 32) {
        float v = g_g[(long long)nd * NC + c];
        ps += v * s1[c];
        pd += v * s2[c];
    }
#pragma unroll
    for (int off = 16; off > 0; off >>= 1) {
        ps += __shfl_xor_sync(0xffffffff, ps, off);
        pd += __shfl_xor_sync(0xffffffff, pd, off);
    }
    if (lane == 0) {
        g_a2s[nd] = ps;
        g_a2d[nd] = pd;
    }
}

// ---------------- layer2 aggregate + bias + log_softmax ---------------------
__global__ void k_agg2(const float* __restrict__ b2, float* __restrict__ out, int n) {
    int nd = blockIdx.x;
    int tid = threadIdx.x;  // blockDim = 64
    __shared__ int src_s[64];
    __shared__ float w_s[64];
    __shared__ float rbuf[2];
    __shared__ float scal[2];
    __shared__ float outv[NC];

    int beg = g_rowptr[nd], end = g_rowptr[nd + 1];
    int deg = end - beg;
    float ad = g_a2d[nd];
    int wid = tid >> 5, lane = tid & 31;

    // max
    float mx = -1e30f;
    for (int i = tid; i < deg; i += 64) {
        int s = g_csrsrc[beg + i];
        mx = fmaxf(mx, lrelu(g_a2s[s] + ad));
    }
#pragma unroll
    for (int off = 16; off > 0; off >>= 1) mx = fmaxf(mx, __shfl_xor_sync(0xffffffff, mx, off));
    if (lane == 0) rbuf[wid] = mx;
    __syncthreads();
    if (tid == 0) scal[0] = fmaxf(rbuf[0], rbuf[1]);
    __syncthreads();
    float m = scal[0];

    // sum(exp)
    float sm = 0.f;
    for (int i = tid; i < deg; i += 64) {
        int s = g_csrsrc[beg + i];
        sm += __expf(lrelu(g_a2s[s] + ad) - m);
    }
#pragma unroll
    for (int off = 16; off > 0; off >>= 1) sm += __shfl_xor_sync(0xffffffff, sm, off);
    if (lane == 0) rbuf[wid] = sm;
    __syncthreads();
    if (tid == 0) scal[1] = 1.f / (rbuf[0] + rbuf[1] + 1e-16f);
    __syncthreads();
    float inv = scal[1];

    // weighted gather
    float acc = 0.f;
    for (int base = 0; base < deg; base += 64) {
        int cnt = min(64, deg - base);
        __syncthreads();
        if (tid < cnt) {
            int s = g_csrsrc[beg + base + tid];
            src_s[tid] = s;
            w_s[tid] = __expf(lrelu(g_a2s[s] + ad) - m) * inv;
        }
        __syncthreads();
        if (tid < NC) {
            for (int e = 0; e < cnt; e++)
                acc += w_s[e] * g_g[(long long)src_s[e] * NC + tid];
        }
    }
    __syncthreads();
    if (tid < NC) outv[tid] = acc + b2[tid];
    __syncthreads();
    if (tid == 0) {
        float m2 = -1e30f;
        for (int c = 0; c < NC; c++) m2 = fmaxf(m2, outv[c]);
        float se = 0.f;
        for (int c = 0; c < NC; c++) se += __expf(outv[c] - m2);
        scal[0] = m2;
        scal[1] = logf(se);
    }
    __syncthreads();
    if (tid < NC) out[(long long)nd * NC + tid] = outv[tid] - scal[0] - scal[1];
}

// ---------------- launch -----------------------------------------------------
extern "C" void kernel_launch(void* const* d_in, const int* in_sizes, int n_in,
                              void* d_out, int out_size) {
    const float* x    = (const float*)d_in[0];
    const void*  ei   = d_in[1];
    const float* W1   = (const float*)d_in[2];
    const float* a1s  = (const float*)d_in[3];
    const float* a1d  = (const float*)d_in[4];
    const float* b1   = (const float*)d_in[5];
    const float* W2   = (const float*)d_in[6];
    const float* a2s  = (const float*)d_in[7];
    const float* a2d  = (const float*)d_in[8];
    const float* b2   = (const float*)d_in[9];
    float* out = (float*)d_out;

    int n = in_sizes[0] / FIN;
    int E = in_sizes[1] / 2;
    int nb = (n + 1023) / 1024;

    k_detect<<<1, 256>>>(ei, n);
    k_gemm1<<<dim3((n + 127) / 128, 2), 256>>>(x, W1, n);
    k_attprep1<<<(n + 7) / 8, 256>>>(a1s, a1d, n);
    k_deginit<<<(n + 255) / 256, 256>>>(n);
    k_hist<<<512, 256>>>(ei, E);
    k_scan1<<<nb, 256>>>(n);
    k_scan2<<<1, 32>>>(nb);
    k_scan3<<<nb, 256>>>(n);
    k_fill<<<832, 256>>>(ei, E, n);
    k_agg1<<<n, 256>>>(b1);
    k_gemm2<<<(n + 255) / 256, 256>>>(W2, n);
    k_attprep2<<<(n + 7) / 8, 256>>>(a2s, a2d, n);
    k_agg2<<<n, 64>>>(b2, out, n);
}

// round 3
// speedup vs baseline: 2.3286x; 2.3286x over previous
#include <cuda_runtime.h>
#include <cuda_bf16.h>
#include <math.h>

#define NN 50000
#define FIN 128
#define F1 256
#define HH 8
#define CH 32
#define NC 40
#define EMAX 1000000

// ---------------- scratch (device globals; no allocation allowed) -----------
__device__ float g_h1[NN * F1];          // layer1 features per node
__device__ float g_h2[NN * F1];          // elu(aggregated + b1)
__device__ float g_as1[NN * HH];
__device__ float g_ad1[NN * HH];
__device__ float g_fm1[NN * HH];
__device__ float g_inv1[NN * HH];
__device__ float g_g[NN * NC];           // layer2 per-node features
__device__ float g_a2s[NN];
__device__ float g_a2d[NN];
__device__ float g_fm2[NN];
__device__ float g_inv2[NN];
__device__ int   g_deg[NN];
__device__ int   g_rowptr[NN + 1];
__device__ int   g_cursor[NN + 1];
__device__ int   g_csrsrc[EMAX];
__device__ int   g_part[64];
__device__ int   g_is64;

// ---------------- helpers ---------------------------------------------------
__device__ __forceinline__ int edge_at(const void* p, long long i, int is64) {
    if (is64) return (int)((const long long*)p)[i];
    return ((const int*)p)[i];
}
__device__ __forceinline__ float lrelu(float v) { return v > 0.f ? v : 0.2f * v; }
__device__ __forceinline__ float eluf(float v) { return v > 0.f ? v : (__expf(v) - 1.f); }

// ---------------- dtype detection ------------------------------------------
__global__ void k_detect(const void* ei, int n) {
    int bad = 0;
    for (int i = threadIdx.x; i < 1024; i += blockDim.x) {
        long long v = ((const long long*)ei)[i];
        if (v < 0 || v >= n) bad = 1;
    }
    int anybad = __syncthreads_or(bad);
    if (threadIdx.x == 0) g_is64 = anybad ? 0 : 1;
}

// ---------------- GEMM1: h1 = x @ W1  (NxFIN @ FINxF1) ----------------------
__global__ void k_gemm1(const float* __restrict__ x, const float* __restrict__ W1, int n) {
    const int BM = 128, BN = 128, BK = 8;
    __shared__ float As[BK][BM];
    __shared__ float Bs[BK][BN];
    int t = threadIdx.x;
    int tx = t % 16, ty = t / 16;
    int bm0 = blockIdx.x * BM, bn0 = blockIdx.y * BN;
    float acc[8][8];
#pragma unroll
    for (int i = 0; i < 8; i++)
#pragma unroll
        for (int j = 0; j < 8; j++) acc[i][j] = 0.f;

    int ar = t >> 1, ac4 = (t & 1) * 4;
    int br = t >> 5, bc4 = (t & 31) * 4;

    for (int kk = 0; kk < FIN; kk += BK) {
        float4 av = make_float4(0.f, 0.f, 0.f, 0.f);
        if (bm0 + ar < n)
            av = *(const float4*)&x[(long long)(bm0 + ar) * FIN + kk + ac4];
        As[ac4 + 0][ar] = av.x;
        As[ac4 + 1][ar] = av.y;
        As[ac4 + 2][ar] = av.z;
        As[ac4 + 3][ar] = av.w;
        float4 bv = *(const float4*)&W1[(long long)(kk + br) * F1 + bn0 + bc4];
        *(float4*)&Bs[br][bc4] = bv;
        __syncthreads();
#pragma unroll
        for (int k = 0; k < BK; k++) {
            float a[8], b[8];
            *(float4*)&a[0] = *(float4*)&As[k][ty * 8];
            *(float4*)&a[4] = *(float4*)&As[k][ty * 8 + 4];
            *(float4*)&b[0] = *(float4*)&Bs[k][tx * 8];
            *(float4*)&b[4] = *(float4*)&Bs[k][tx * 8 + 4];
#pragma unroll
            for (int i = 0; i < 8; i++)
#pragma unroll
                for (int j = 0; j < 8; j++) acc[i][j] += a[i] * b[j];
        }
        __syncthreads();
    }
#pragma unroll
    for (int i = 0; i < 8; i++) {
        int row = bm0 + ty * 8 + i;
        if (row < n) {
            *(float4*)&g_h1[(long long)row * F1 + bn0 + tx * 8]     = *(float4*)&acc[i][0];
            *(float4*)&g_h1[(long long)row * F1 + bn0 + tx * 8 + 4] = *(float4*)&acc[i][4];
        }
    }
}

// ---------------- attention prep layer1: as1/ad1 ----------------------------
__global__ void k_attprep1(const float* __restrict__ a1src, const float* __restrict__ a1dst, int n) {
    __shared__ float s1[F1], s2[F1];
    int t = threadIdx.x;
    s1[t] = a1src[t];
    s2[t] = a1dst[t];
    __syncthreads();
    int nd = blockIdx.x * 8 + (t >> 5);
    int lane = t & 31;
    if (nd >= n) return;
#pragma unroll
    for (int h = 0; h < HH; h++) {
        int idx = h * 32 + lane;
        float v = g_h1[(long long)nd * F1 + idx];
        float ps = v * s1[idx];
        float pd = v * s2[idx];
#pragma unroll
        for (int off = 16; off > 0; off >>= 1) {
            ps += __shfl_xor_sync(0xffffffff, ps, off);
            pd += __shfl_xor_sync(0xffffffff, pd, off);
        }
        if (lane == 0) {
            g_as1[nd * HH + h] = ps;
            g_ad1[nd * HH + h] = pd;
        }
    }
}

// ---------------- CSR construction ------------------------------------------
__global__ void k_deginit(int n) {
    int i = blockIdx.x * blockDim.x + threadIdx.x;
    if (i < n) g_deg[i] = 1;  // self-loop
}
__global__ void k_hist(const void* ei, int E) {
    int is64 = g_is64;
    for (int i = blockIdx.x * blockDim.x + threadIdx.x; i < E; i += gridDim.x * blockDim.x) {
        int d = edge_at(ei, (long long)E + i, is64);
        atomicAdd(&g_deg[d], 1);
    }
}
__global__ void k_scan1(int n) {
    __shared__ int ssum[256];
    int b = blockIdx.x, t = threadIdx.x;
    int base = b * 1024 + t * 4;
    int v[4];
    int tsum = 0;
#pragma unroll
    for (int j = 0; j < 4; j++) {
        int idx = base + j;
        v[j] = (idx < n) ? g_deg[idx] : 0;
        tsum += v[j];
    }
    ssum[t] = tsum;
    __syncthreads();
    for (int off = 1; off < 256; off <<= 1) {
        int x = (t >= off) ? ssum[t - off] : 0;
        __syncthreads();
        ssum[t] += x;
        __syncthreads();
    }
    int run = ssum[t] - tsum;
#pragma unroll
    for (int j = 0; j < 4; j++) {
        run += v[j];
        if (base + j < n) g_rowptr[base + j + 1] = run;
    }
    if (t == 255) g_part[b] = ssum[255];
}
__global__ void k_scan2(int nb) {
    if (threadIdx.x == 0 && blockIdx.x == 0) {
        int run = 0;
        for (int b = 0; b < nb; b++) {
            int t = g_part[b];
            g_part[b] = run;
            run += t;
        }
        g_rowptr[0] = 0;
        g_cursor[0] = 0;
    }
}
__global__ void k_scan3(int n) {
    int b = blockIdx.x, t = threadIdx.x;
    int off = g_part[b];
    int base = b * 1024 + t * 4;
#pragma unroll
    for (int j = 0; j < 4; j++) {
        int idx = base + j;
        if (idx < n) {
            int v = g_rowptr[idx + 1] + off;
            g_rowptr[idx + 1] = v;
            g_cursor[idx + 1] = v;
        }
    }
}
__global__ void k_fill(const void* ei, int E, int n) {
    int is64 = g_is64;
    int total = E + n;
    for (int i = blockIdx.x * blockDim.x + threadIdx.x; i < total; i += gridDim.x * blockDim.x) {
        int s, d;
        if (i < E) {
            s = edge_at(ei, i, is64);
            d = edge_at(ei, (long long)E + i, is64);
        } else {
            s = d = i - E;
        }
        int p = atomicAdd(&g_cursor[d], 1);
        g_csrsrc[p] = s;
    }
}

// ---------------- layer1 softmax normalizers (warp per node) ----------------
__global__ void k_maxsum1(int n) {
    int w = (blockIdx.x * blockDim.x + threadIdx.x) >> 5;
    int lane = threadIdx.x & 31;
    if (w >= n) return;
    int beg = g_rowptr[w], end = g_rowptr[w + 1];
    int h = lane & 7, slot = lane >> 3;   // 4 edge-slots x 8 heads
    float ad = g_ad1[w * HH + h];
    float mx = -1e30f;
    for (int e = beg + slot; e < end; e += 4) {
        int s = g_csrsrc[e];
        mx = fmaxf(mx, lrelu(g_as1[s * HH + h] + ad));
    }
    mx = fmaxf(mx, __shfl_xor_sync(0xffffffffu, mx, 8));
    mx = fmaxf(mx, __shfl_xor_sync(0xffffffffu, mx, 16));
    float sm = 0.f;
    for (int e = beg + slot; e < end; e += 4) {
        int s = g_csrsrc[e];
        sm += __expf(lrelu(g_as1[s * HH + h] + ad) - mx);
    }
    sm += __shfl_xor_sync(0xffffffffu, sm, 8);
    sm += __shfl_xor_sync(0xffffffffu, sm, 16);
    if (lane < HH) {
        g_fm1[w * HH + lane] = mx;
        g_inv1[w * HH + lane] = 1.f / (sm + 1e-16f);
    }
}

// ---------------- layer1 fused weight+gather+bias+elu (warp per node) -------
__global__ void k_gather1(const float* __restrict__ b1, int n) {
    int w = (blockIdx.x * blockDim.x + threadIdx.x) >> 5;
    int lane = threadIdx.x & 31;
    if (w >= n) return;
    int beg = g_rowptr[w], end = g_rowptr[w + 1];
    int deg = end - beg;
    int hlo = lane >> 3, hhi = hlo + 4;   // heads of the two float4 chunks this lane owns
    float ad_lo = g_ad1[w * HH + hlo], ad_hi = g_ad1[w * HH + hhi];
    float fm_lo = g_fm1[w * HH + hlo], fm_hi = g_fm1[w * HH + hhi];
    float iv_lo = g_inv1[w * HH + hlo], iv_hi = g_inv1[w * HH + hhi];
    float4 alo = make_float4(0.f, 0.f, 0.f, 0.f);
    float4 ahi = make_float4(0.f, 0.f, 0.f, 0.f);
    const float4* h1v = (const float4*)g_h1;
    for (int base = 0; base < deg; base += 32) {
        int cnt = min(32, deg - base);
        int s_l = 0;
        if (lane < cnt) s_l = g_csrsrc[beg + base + lane];
#pragma unroll 4
        for (int j = 0; j < cnt; j++) {
            int s = __shfl_sync(0xffffffffu, s_l, j);
            float wlo = __expf(lrelu(g_as1[s * HH + hlo] + ad_lo) - fm_lo) * iv_lo;
            float whi = __expf(lrelu(g_as1[s * HH + hhi] + ad_hi) - fm_hi) * iv_hi;
            float4 xlo = h1v[(long long)s * 64 + lane];
            float4 xhi = h1v[(long long)s * 64 + lane + 32];
            alo.x += wlo * xlo.x; alo.y += wlo * xlo.y;
            alo.z += wlo * xlo.z; alo.w += wlo * xlo.w;
            ahi.x += whi * xhi.x; ahi.y += whi * xhi.y;
            ahi.z += whi * xhi.z; ahi.w += whi * xhi.w;
        }
    }
    float4 blo = ((const float4*)b1)[lane];
    float4 bhi = ((const float4*)b1)[lane + 32];
    float4 r0, r1;
    r0.x = eluf(alo.x + blo.x); r0.y = eluf(alo.y + blo.y);
    r0.z = eluf(alo.z + blo.z); r0.w = eluf(alo.w + blo.w);
    r1.x = eluf(ahi.x + bhi.x); r1.y = eluf(ahi.y + bhi.y);
    r1.z = eluf(ahi.z + bhi.z); r1.w = eluf(ahi.w + bhi.w);
    ((float4*)g_h2)[(long long)w * 64 + lane] = r0;
    ((float4*)g_h2)[(long long)w * 64 + lane + 32] = r1;
}

// ---------------- GEMM2: g = h2 @ W2  (NxF1 @ F1xNC) ------------------------
__global__ void k_gemm2(const float* __restrict__ W2, int n) {
    const int BM = 256, BK = 16;
    __shared__ float h2s[BM][BK + 1];
    __shared__ float W2s[BK * NC];
    int t = threadIdx.x;
    int rg = t >> 2;   // 0..63  -> 4 rows each
    int q = t & 3;     // 0..3   -> 10 cols each
    int bm0 = blockIdx.x * BM;
    float acc[4][10];
#pragma unroll
    for (int i = 0; i < 4; i++)
#pragma unroll
        for (int j = 0; j < 10; j++) acc[i][j] = 0.f;

    for (int kc = 0; kc < F1; kc += BK) {
#pragma unroll
        for (int j = 0; j < 4; j++) {
            int li = t + 256 * j;
            int row = li >> 2;
            int c4 = li & 3;
            float4 v = make_float4(0.f, 0.f, 0.f, 0.f);
            if (bm0 + row < n)
                v = *(const float4*)&g_h2[(long long)(bm0 + row) * F1 + kc + c4 * 4];
            h2s[row][c4 * 4 + 0] = v.x;
            h2s[row][c4 * 4 + 1] = v.y;
            h2s[row][c4 * 4 + 2] = v.z;
            h2s[row][c4 * 4 + 3] = v.w;
        }
        if (t < 160)
            *(float4*)&W2s[t * 4] = *(const float4*)&W2[kc * NC + t * 4];
        __syncthreads();
#pragma unroll
        for (int k = 0; k < BK; k++) {
            float a0 = h2s[rg * 4 + 0][k];
            float a1 = h2s[rg * 4 + 1][k];
            float a2 = h2s[rg * 4 + 2][k];
            float a3 = h2s[rg * 4 + 3][k];
#pragma unroll
            for (int j = 0; j < 10; j++) {
                float b = W2s[k * NC + q * 10 + j];
                acc[0][j] += a0 * b;
                acc[1][j] += a1 * b;
                acc[2][j] += a2 * b;
                acc[3][j] += a3 * b;
            }
        }
        __syncthreads();
    }
#pragma unroll
    for (int i = 0; i < 4; i++) {
        int row = bm0 + rg * 4 + i;
        if (row < n) {
#pragma unroll
            for (int j = 0; j < 10; j++) g_g[(long long)row * NC + q * 10 + j] = acc[i][j];
        }
    }
}

// ---------------- attention prep layer2 -------------------------------------
__global__ void k_attprep2(const float* __restrict__ a2src, const float* __restrict__ a2dst, int n) {
    __shared__ float s1[NC], s2[NC];
    int t = threadIdx.x;
    if (t < NC) {
        s1[t] = a2src[t];
        s2[t] = a2dst[t];
    }
    __syncthreads();
    int nd = blockIdx.x * 8 + (t >> 5);
    int lane = t & 31;
    if (nd >= n) return;
    float ps = 0.f, pd = 0.f;
    for (int c = lane; c < NC; c += 32) {
        float v = g_g[(long long)nd * NC + c];
        ps += v * s1[c];
        pd += v * s2[c];
    }
#pragma unroll
    for (int off = 16; off > 0; off >>= 1) {
        ps += __shfl_xor_sync(0xffffffff, ps, off);
        pd += __shfl_xor_sync(0xffffffff, pd, off);
    }
    if (lane == 0) {
        g_a2s[nd] = ps;
        g_a2d[nd] = pd;
    }
}

// ---------------- layer2 softmax normalizers (warp per node) ----------------
__global__ void k_maxsum2(int n) {
    int w = (blockIdx.x * blockDim.x + threadIdx.x) >> 5;
    int lane = threadIdx.x & 31;
    if (w >= n) return;
    int beg = g_rowptr[w], end = g_rowptr[w + 1];
    float ad = g_a2d[w];
    float mx = -1e30f;
    for (int e = beg + lane; e < end; e += 32)
        mx = fmaxf(mx, lrelu(g_a2s[g_csrsrc[e]] + ad));
#pragma unroll
    for (int off = 16; off > 0; off >>= 1)
        mx = fmaxf(mx, __shfl_xor_sync(0xffffffffu, mx, off));
    float sm = 0.f;
    for (int e = beg + lane; e < end; e += 32)
        sm += __expf(lrelu(g_a2s[g_csrsrc[e]] + ad) - mx);
#pragma unroll
    for (int off = 16; off > 0; off >>= 1)
        sm += __shfl_xor_sync(0xffffffffu, sm, off);
    if (lane == 0) {
        g_fm2[w] = mx;
        g_inv2[w] = 1.f / (sm + 1e-16f);
    }
}

// ---------------- layer2 fused gather + bias + log_softmax (warp per node) --
__global__ void k_gather2(const float* __restrict__ b2, float* __restrict__ out, int n) {
    int w = (blockIdx.x * blockDim.x + threadIdx.x) >> 5;
    int lane = threadIdx.x & 31;
    if (w >= n) return;
    int beg = g_rowptr[w], end = g_rowptr[w + 1];
    int deg = end - beg;
    float ad = g_a2d[w], m = g_fm2[w], iv = g_inv2[w];
    float acc_lo = 0.f, acc_hi = 0.f;
    for (int base = 0; base < deg; base += 32) {
        int cnt = min(32, deg - base);
        int s_l = 0;
        if (lane < cnt) s_l = g_csrsrc[beg + base + lane];
#pragma unroll 4
        for (int j = 0; j < cnt; j++) {
            int s = __shfl_sync(0xffffffffu, s_l, j);
            float wg = __expf(lrelu(g_a2s[s] + ad) - m) * iv;
            acc_lo += wg * g_g[(long long)s * NC + lane];
            if (lane < 8) acc_hi += wg * g_g[(long long)s * NC + 32 + lane];
        }
    }
    float v_lo = acc_lo + b2[lane];
    float v_hi = (lane < 8) ? (acc_hi + b2[32 + lane]) : -1e30f;
    float lm = fmaxf(v_lo, v_hi);
#pragma unroll
    for (int off = 16; off > 0; off >>= 1)
        lm = fmaxf(lm, __shfl_xor_sync(0xffffffffu, lm, off));
    float se = __expf(v_lo - lm) + ((lane < 8) ? __expf(v_hi - lm) : 0.f);
#pragma unroll
    for (int off = 16; off > 0; off >>= 1)
        se += __shfl_xor_sync(0xffffffffu, se, off);
    float ls = lm + logf(se);
    out[(long long)w * NC + lane] = v_lo - ls;
    if (lane < 8) out[(long long)w * NC + 32 + lane] = v_hi - ls;
}

// ---------------- launch -----------------------------------------------------
extern "C" void kernel_launch(void* const* d_in, const int* in_sizes, int n_in,
                              void* d_out, int out_size) {
    const float* x    = (const float*)d_in[0];
    const void*  ei   = d_in[1];
    const float* W1   = (const float*)d_in[2];
    const float* a1s  = (const float*)d_in[3];
    const float* a1d  = (const float*)d_in[4];
    const float* b1   = (const float*)d_in[5];
    const float* W2   = (const float*)d_in[6];
    const float* a2s  = (const float*)d_in[7];
    const float* a2d  = (const float*)d_in[8];
    const float* b2   = (const float*)d_in[9];
    float* out = (float*)d_out;

    int n = in_sizes[0] / FIN;
    int E = in_sizes[1] / 2;
    int nb = (n + 1023) / 1024;
    int wpb = (n + 7) / 8;  // warp-per-node grids (8 warps / 256-thread block)

    k_detect<<<1, 256>>>(ei, n);
    k_gemm1<<<dim3((n + 127) / 128, 2), 256>>>(x, W1, n);
    k_attprep1<<<(n + 7) / 8, 256>>>(a1s, a1d, n);
    k_deginit<<<(n + 255) / 256, 256>>>(n);
    k_hist<<<512, 256>>>(ei, E);
    k_scan1<<<nb, 256>>>(n);
    k_scan2<<<1, 32>>>(nb);
    k_scan3<<<nb, 256>>>(n);
    k_fill<<<832, 256>>>(ei, E, n);
    k_maxsum1<<<wpb, 256>>>(n);
    k_gather1<<<wpb, 256>>>(b1, n);
    k_gemm2<<<(n + 255) / 256, 256>>>(W2, n);
    k_attprep2<<<(n + 7) / 8, 256>>>(a2s, a2d, n);
    k_maxsum2<<<wpb, 256>>>(n);
    k_gather2<<<wpb, 256>>>(b2, out, n);
}

// round 6
// speedup vs baseline: 3.0405x; 1.3057x over previous
#include <cuda_runtime.h>
#include <cuda_bf16.h>
#include <math.h>

#define NN 50000
#define FIN 128
#define F1 256
#define HH 8
#define CH 32
#define NC 40
#define EMAX 1000000

// ---------------- scratch (device globals; no allocation allowed) -----------
__device__ __nv_bfloat16 g_h1bf[NN * F1];  // layer1 features, bf16, lane-permuted layout
__device__ float g_h2[NN * F1];            // elu(aggregated + b1)
__device__ float g_as1[NN * HH];
__device__ float g_ad1[NN * HH];
__device__ float g_fm1[NN * HH];
__device__ float g_inv1[NN * HH];
__device__ float g_g[NN * NC];             // layer2 per-node features
__device__ float g_a2s[NN];
__device__ float g_a2d[NN];
__device__ float g_fm2[NN];
__device__ float g_inv2[NN];
__device__ int   g_deg[NN];
__device__ int   g_rowptr[NN + 1];
__device__ int   g_cursor[NN + 1];
__device__ int   g_csrsrc[EMAX];
__device__ int   g_part[64];
__device__ int   g_is64;

// ---------------- helpers ---------------------------------------------------
__device__ __forceinline__ int edge_at(const void* p, long long i, int is64) {
    if (is64) return (int)((const long long*)p)[i];
    return ((const int*)p)[i];
}
__device__ __forceinline__ float lrelu(float v) { return v > 0.f ? v : 0.2f * v; }
__device__ __forceinline__ float eluf(float v) { return v > 0.f ? v : (__expf(v) - 1.f); }

// ---------------- dtype detection ------------------------------------------
__global__ void k_detect(const void* ei, int n) {
    int bad = 0;
    for (int i = threadIdx.x; i < 1024; i += blockDim.x) {
        long long v = ((const long long*)ei)[i];
        if (v < 0 || v >= n) bad = 1;
    }
    int anybad = __syncthreads_or(bad);
    if (threadIdx.x == 0) g_is64 = anybad ? 0 : 1;
}

// ---------------- GEMM1 fused: h1 = x@W1, att scores, bf16 permuted output --
// BM=64, BN=256 (full width), BK=16, 256 threads, 8x8 per thread.
__global__ void k_gemm1f(const float* __restrict__ x, const float* __restrict__ W1,
                         const float* __restrict__ a1s_, const float* __restrict__ a1d_, int n) {
    const int BM = 64, BK = 16;
    __shared__ float As[BK][BM];      // stride 256B -> float4 reads stay 16B-aligned
    __shared__ float Bs[BK][F1];
    __shared__ float sas[BM][HH];
    __shared__ float sad[BM][HH];
    int t = threadIdx.x;
    int tx = t & 31;        // col group: cols tx*8..tx*8+7
    int ty = t >> 5;        // row group: rows ty*8..ty*8+7
    int bm0 = blockIdx.x * BM;

    // zero score accumulators
    for (int i = t; i < BM * HH; i += 256) {
        ((float*)sas)[i] = 0.f;
        ((float*)sad)[i] = 0.f;
    }

    float acc[8][8];
#pragma unroll
    for (int i = 0; i < 8; i++)
#pragma unroll
        for (int j = 0; j < 8; j++) acc[i][j] = 0.f;

    int arow = t >> 2, akc = (t & 3) * 4;

    for (int kk = 0; kk < FIN; kk += BK) {
        float4 av = make_float4(0.f, 0.f, 0.f, 0.f);
        if (bm0 + arow < n)
            av = *(const float4*)&x[(long long)(bm0 + arow) * FIN + kk + akc];
        As[akc + 0][arow] = av.x;
        As[akc + 1][arow] = av.y;
        As[akc + 2][arow] = av.z;
        As[akc + 3][arow] = av.w;
#pragma unroll
        for (int j = 0; j < 4; j++) {
            int f4 = t + 256 * j;
            int brow = f4 >> 6, bcol = (f4 & 63) * 4;
            *(float4*)&Bs[brow][bcol] = *(const float4*)&W1[(long long)(kk + brow) * F1 + bcol];
        }
        __syncthreads();
#pragma unroll
        for (int k = 0; k < BK; k++) {
            float a[8], b[8];
            *(float4*)&a[0] = *(float4*)&As[k][ty * 8];
            *(float4*)&a[4] = *(float4*)&As[k][ty * 8 + 4];
            *(float4*)&b[0] = *(float4*)&Bs[k][tx * 8];
            *(float4*)&b[4] = *(float4*)&Bs[k][tx * 8 + 4];
#pragma unroll
            for (int i = 0; i < 8; i++)
#pragma unroll
                for (int j = 0; j < 8; j++) acc[i][j] += a[i] * b[j];
        }
        __syncthreads();
    }

    // attention coefficients for this thread's 8 columns (all in one head)
    float cs[8], cd[8];
#pragma unroll
    for (int j = 0; j < 8; j++) {
        cs[j] = a1s_[tx * 8 + j];
        cd[j] = a1d_[tx * 8 + j];
    }
    int hh = tx >> 2;

    // bf16 permuted store: thread's 8 cols -> elems base_e..+3 and base_e+8..+11
    int base_e = (tx < 16) ? tx * 16 : (tx - 16) * 16 + 4;
#pragma unroll
    for (int i = 0; i < 8; i++) {
        int r = ty * 8 + i;
        int row = bm0 + r;
        float ps = 0.f, pd = 0.f;
#pragma unroll
        for (int j = 0; j < 8; j++) {
            ps += acc[i][j] * cs[j];
            pd += acc[i][j] * cd[j];
        }
        atomicAdd(&sas[r][hh], ps);
        atomicAdd(&sad[r][hh], pd);
        if (row < n) {
            __nv_bfloat162 p01 = __floats2bfloat162_rn(acc[i][0], acc[i][1]);
            __nv_bfloat162 p23 = __floats2bfloat162_rn(acc[i][2], acc[i][3]);
            __nv_bfloat162 p45 = __floats2bfloat162_rn(acc[i][4], acc[i][5]);
            __nv_bfloat162 p67 = __floats2bfloat162_rn(acc[i][6], acc[i][7]);
            __nv_bfloat162* dst = (__nv_bfloat162*)&g_h1bf[(long long)row * F1 + base_e];
            dst[0] = p01;
            dst[1] = p23;
            __nv_bfloat162* dst2 = (__nv_bfloat162*)&g_h1bf[(long long)row * F1 + base_e + 8];
            dst2[0] = p45;
            dst2[1] = p67;
        }
    }
    __syncthreads();
    for (int idx = t; idx < BM * HH; idx += 256) {
        int r = idx >> 3, h = idx & 7;
        if (bm0 + r < n) {
            g_as1[(bm0 + r) * HH + h] = sas[r][h];
            g_ad1[(bm0 + r) * HH + h] = sad[r][h];
        }
    }
}

// ---------------- CSR construction ------------------------------------------
__global__ void k_deginit(int n) {
    int i = blockIdx.x * blockDim.x + threadIdx.x;
    if (i < n) g_deg[i] = 1;  // self-loop
}
__global__ void k_hist(const void* ei, int E) {
    int is64 = g_is64;
    for (int i = blockIdx.x * blockDim.x + threadIdx.x; i < E; i += gridDim.x * blockDim.x) {
        int d = edge_at(ei, (long long)E + i, is64);
        atomicAdd(&g_deg[d], 1);
    }
}
__global__ void k_scan1(int n) {
    __shared__ int ssum[256];
    int b = blockIdx.x, t = threadIdx.x;
    int base = b * 1024 + t * 4;
    int v[4];
    int tsum = 0;
#pragma unroll
    for (int j = 0; j < 4; j++) {
        int idx = base + j;
        v[j] = (idx < n) ? g_deg[idx] : 0;
        tsum += v[j];
    }
    ssum[t] = tsum;
    __syncthreads();
    for (int off = 1; off < 256; off <<= 1) {
        int x = (t >= off) ? ssum[t - off] : 0;
        __syncthreads();
        ssum[t] += x;
        __syncthreads();
    }
    int run = ssum[t] - tsum;
#pragma unroll
    for (int j = 0; j < 4; j++) {
        run += v[j];
        if (base + j < n) g_rowptr[base + j + 1] = run;
    }
    if (t == 255) g_part[b] = ssum[255];
}
__global__ void k_scan2(int nb) {
    if (threadIdx.x == 0 && blockIdx.x == 0) {
        int run = 0;
        for (int b = 0; b < nb; b++) {
            int t = g_part[b];
            g_part[b] = run;
            run += t;
        }
        g_rowptr[0] = 0;
        g_cursor[0] = 0;
    }
}
__global__ void k_scan3(int n) {
    int b = blockIdx.x, t = threadIdx.x;
    int off = g_part[b];
    int base = b * 1024 + t * 4;
#pragma unroll
    for (int j = 0; j < 4; j++) {
        int idx = base + j;
        if (idx < n) {
            int v = g_rowptr[idx + 1] + off;
            g_rowptr[idx + 1] = v;
            g_cursor[idx + 1] = v;
        }
    }
}
__global__ void k_fill(const void* ei, int E, int n) {
    int is64 = g_is64;
    int total = E + n;
    for (int i = blockIdx.x * blockDim.x + threadIdx.x; i < total; i += gridDim.x * blockDim.x) {
        int s, d;
        if (i < E) {
            s = edge_at(ei, i, is64);
            d = edge_at(ei, (long long)E + i, is64);
        } else {
            s = d = i - E;
        }
        int p = atomicAdd(&g_cursor[d], 1);
        g_csrsrc[p] = s;
    }
}

// ---------------- layer1 softmax normalizers (warp per node) ----------------
__global__ void k_maxsum1(int n) {
    int w = (blockIdx.x * blockDim.x + threadIdx.x) >> 5;
    int lane = threadIdx.x & 31;
    if (w >= n) return;
    int beg = g_rowptr[w], end = g_rowptr[w + 1];
    int h = lane & 7, slot = lane >> 3;   // 4 edge-slots x 8 heads
    float ad = g_ad1[w * HH + h];
    float mx = -1e30f;
    for (int e = beg + slot; e < end; e += 4) {
        int s = g_csrsrc[e];
        mx = fmaxf(mx, lrelu(g_as1[s * HH + h] + ad));
    }
    mx = fmaxf(mx, __shfl_xor_sync(0xffffffffu, mx, 8));
    mx = fmaxf(mx, __shfl_xor_sync(0xffffffffu, mx, 16));
    float sm = 0.f;
    for (int e = beg + slot; e < end; e += 4) {
        int s = g_csrsrc[e];
        sm += __expf(lrelu(g_as1[s * HH + h] + ad) - mx);
    }
    sm += __shfl_xor_sync(0xffffffffu, sm, 8);
    sm += __shfl_xor_sync(0xffffffffu, sm, 16);
    if (lane < HH) {
        g_fm1[w * HH + lane] = mx;
        g_inv1[w * HH + lane] = 1.f / (sm + 1e-16f);
    }
}

// ---------------- layer1 fused weight+gather+bias+elu (warp per node) -------
// Each lane reads ONE uint4 (8 bf16) per edge: feats {4l..4l+3, 128+4l..128+4l+3}.
__global__ void k_gather1(const float* __restrict__ b1, int n) {
    int w = (blockIdx.x * blockDim.x + threadIdx.x) >> 5;
    int lane = threadIdx.x & 31;
    if (w >= n) return;
    int beg = g_rowptr[w], end = g_rowptr[w + 1];
    int deg = end - beg;
    int hlo = lane >> 3, hhi = hlo + 4;
    float ad_lo = g_ad1[w * HH + hlo], ad_hi = g_ad1[w * HH + hhi];
    float fm_lo = g_fm1[w * HH + hlo], fm_hi = g_fm1[w * HH + hhi];
    float iv_lo = g_inv1[w * HH + hlo], iv_hi = g_inv1[w * HH + hhi];
    float4 alo = make_float4(0.f, 0.f, 0.f, 0.f);
    float4 ahi = make_float4(0.f, 0.f, 0.f, 0.f);
    const uint4* h1bv = (const uint4*)g_h1bf;
    for (int base = 0; base < deg; base += 32) {
        int cnt = min(32, deg - base);
        int s_l = 0;
        if (lane < cnt) s_l = g_csrsrc[beg + base + lane];
#pragma unroll 4
        for (int j = 0; j < cnt; j++) {
            int s = __shfl_sync(0xffffffffu, s_l, j);
            float wlo = __expf(lrelu(g_as1[s * HH + hlo] + ad_lo) - fm_lo) * iv_lo;
            float whi = __expf(lrelu(g_as1[s * HH + hhi] + ad_hi) - fm_hi) * iv_hi;
            uint4 v = h1bv[(long long)s * 32 + lane];
            float2 x0 = __bfloat1622float2(*(__nv_bfloat162*)&v.x);
            float2 x1 = __bfloat1622float2(*(__nv_bfloat162*)&v.y);
            float2 x2 = __bfloat1622float2(*(__nv_bfloat162*)&v.z);
            float2 x3 = __bfloat1622float2(*(__nv_bfloat162*)&v.w);
            alo.x += wlo * x0.x; alo.y += wlo * x0.y;
            alo.z += wlo * x1.x; alo.w += wlo * x1.y;
            ahi.x += whi * x2.x; ahi.y += whi * x2.y;
            ahi.z += whi * x3.x; ahi.w += whi * x3.y;
        }
    }
    float4 blo = ((const float4*)b1)[lane];
    float4 bhi = ((const float4*)b1)[lane + 32];
    float4 r0, r1;
    r0.x = eluf(alo.x + blo.x); r0.y = eluf(alo.y + blo.y);
    r0.z = eluf(alo.z + blo.z); r0.w = eluf(alo.w + blo.w);
    r1.x = eluf(ahi.x + bhi.x); r1.y = eluf(ahi.y + bhi.y);
    r1.z = eluf(ahi.z + bhi.z); r1.w = eluf(ahi.w + bhi.w);
    ((float4*)g_h2)[(long long)w * 64 + lane] = r0;
    ((float4*)g_h2)[(long long)w * 64 + lane + 32] = r1;
}

// ---------------- GEMM2 fused: g = h2@W2 + layer2 att scores ----------------
__global__ void k_gemm2f(const float* __restrict__ W2,
                         const float* __restrict__ a2s_, const float* __restrict__ a2d_, int n) {
    const int BM = 256, BK = 16;
    __shared__ float h2s[BM][BK + 1];
    __shared__ float W2s[BK * NC];
    __shared__ float s2s[BM];
    __shared__ float s2d[BM];
    int t = threadIdx.x;
    int rg = t >> 2;   // 0..63  -> 4 rows each
    int q = t & 3;     // 0..3   -> 10 cols each
    int bm0 = blockIdx.x * BM;
    s2s[t] = 0.f;
    s2d[t] = 0.f;
    float acc[4][10];
#pragma unroll
    for (int i = 0; i < 4; i++)
#pragma unroll
        for (int j = 0; j < 10; j++) acc[i][j] = 0.f;

    for (int kc = 0; kc < F1; kc += BK) {
#pragma unroll
        for (int j = 0; j < 4; j++) {
            int li = t + 256 * j;
            int row = li >> 2;
            int c4 = li & 3;
            float4 v = make_float4(0.f, 0.f, 0.f, 0.f);
            if (bm0 + row < n)
                v = *(const float4*)&g_h2[(long long)(bm0 + row) * F1 + kc + c4 * 4];
            h2s[row][c4 * 4 + 0] = v.x;
            h2s[row][c4 * 4 + 1] = v.y;
            h2s[row][c4 * 4 + 2] = v.z;
            h2s[row][c4 * 4 + 3] = v.w;
        }
        if (t < 160)
            *(float4*)&W2s[t * 4] = *(const float4*)&W2[kc * NC + t * 4];
        __syncthreads();
#pragma unroll
        for (int k = 0; k < BK; k++) {
            float a0 = h2s[rg * 4 + 0][k];
            float a1 = h2s[rg * 4 + 1][k];
            float a2 = h2s[rg * 4 + 2][k];
            float a3 = h2s[rg * 4 + 3][k];
#pragma unroll
            for (int j = 0; j < 10; j++) {
                float b = W2s[k * NC + q * 10 + j];
                acc[0][j] += a0 * b;
                acc[1][j] += a1 * b;
                acc[2][j] += a2 * b;
                acc[3][j] += a3 * b;
            }
        }
        __syncthreads();
    }
    float cs[10], cd[10];
#pragma unroll
    for (int j = 0; j < 10; j++) {
        cs[j] = a2s_[q * 10 + j];
        cd[j] = a2d_[q * 10 + j];
    }
#pragma unroll
    for (int i = 0; i < 4; i++) {
        int r = rg * 4 + i;
        int row = bm0 + r;
        float ps = 0.f, pd = 0.f;
#pragma unroll
        for (int j = 0; j < 10; j++) {
            ps += acc[i][j] * cs[j];
            pd += acc[i][j] * cd[j];
        }
        atomicAdd(&s2s[r], ps);
        atomicAdd(&s2d[r], pd);
        if (row < n) {
#pragma unroll
            for (int j = 0; j < 10; j++) g_g[(long long)row * NC + q * 10 + j] = acc[i][j];
        }
    }
    __syncthreads();
    if (bm0 + t < n) {
        g_a2s[bm0 + t] = s2s[t];
        g_a2d[bm0 + t] = s2d[t];
    }
}

// ---------------- layer2 softmax normalizers (warp per node) ----------------
__global__ void k_maxsum2(int n) {
    int w = (blockIdx.x * blockDim.x + threadIdx.x) >> 5;
    int lane = threadIdx.x & 31;
    if (w >= n) return;
    int beg = g_rowptr[w], end = g_rowptr[w + 1];
    float ad = g_a2d[w];
    float mx = -1e30f;
    for (int e = beg + lane; e < end; e += 32)
        mx = fmaxf(mx, lrelu(g_a2s[g_csrsrc[e]] + ad));
#pragma unroll
    for (int off = 16; off > 0; off >>= 1)
        mx = fmaxf(mx, __shfl_xor_sync(0xffffffffu, mx, off));
    float sm = 0.f;
    for (int e = beg + lane; e < end; e += 32)
        sm += __expf(lrelu(g_a2s[g_csrsrc[e]] + ad) - mx);
#pragma unroll
    for (int off = 16; off > 0; off >>= 1)
        sm += __shfl_xor_sync(0xffffffffu, sm, off);
    if (lane == 0) {
        g_fm2[w] = mx;
        g_inv2[w] = 1.f / (sm + 1e-16f);
    }
}

// ---------------- layer2 fused gather + bias + log_softmax (warp per node) --
__global__ void k_gather2(const float* __restrict__ b2, float* __restrict__ out, int n) {
    int w = (blockIdx.x * blockDim.x + threadIdx.x) >> 5;
    int lane = threadIdx.x & 31;
    if (w >= n) return;
    int beg = g_rowptr[w], end = g_rowptr[w + 1];
    int deg = end - beg;
    float ad = g_a2d[w], m = g_fm2[w], iv = g_inv2[w];
    float acc_lo = 0.f, acc_hi = 0.f;
    for (int base = 0; base < deg; base += 32) {
        int cnt = min(32, deg - base);
        int s_l = 0;
        if (lane < cnt) s_l = g_csrsrc[beg + base + lane];
#pragma unroll 4
        for (int j = 0; j < cnt; j++) {
            int s = __shfl_sync(0xffffffffu, s_l, j);
            float wg = __expf(lrelu(g_a2s[s] + ad) - m) * iv;
            acc_lo += wg * g_g[(long long)s * NC + lane];
            if (lane < 8) acc_hi += wg * g_g[(long long)s * NC + 32 + lane];
        }
    }
    float v_lo = acc_lo + b2[lane];
    float v_hi = (lane < 8) ? (acc_hi + b2[32 + lane]) : -1e30f;
    float lm = fmaxf(v_lo, v_hi);
#pragma unroll
    for (int off = 16; off > 0; off >>= 1)
        lm = fmaxf(lm, __shfl_xor_sync(0xffffffffu, lm, off));
    float se = __expf(v_lo - lm) + ((lane < 8) ? __expf(v_hi - lm) : 0.f);
#pragma unroll
    for (int off = 16; off > 0; off >>= 1)
        se += __shfl_xor_sync(0xffffffffu, se, off);
    float ls = lm + logf(se);
    out[(long long)w * NC + lane] = v_lo - ls;
    if (lane < 8) out[(long long)w * NC + 32 + lane] = v_hi - ls;
}

// ---------------- launch -----------------------------------------------------
extern "C" void kernel_launch(void* const* d_in, const int* in_sizes, int n_in,
                              void* d_out, int out_size) {
    const float* x    = (const float*)d_in[0];
    const void*  ei   = d_in[1];
    const float* W1   = (const float*)d_in[2];
    const float* a1s  = (const float*)d_in[3];
    const float* a1d  = (const float*)d_in[4];
    const float* b1   = (const float*)d_in[5];
    const float* W2   = (const float*)d_in[6];
    const float* a2s  = (const float*)d_in[7];
    const float* a2d  = (const float*)d_in[8];
    const float* b2   = (const float*)d_in[9];
    float* out = (float*)d_out;

    int n = in_sizes[0] / FIN;
    int E = in_sizes[1] / 2;
    int nb = (n + 1023) / 1024;
    int wpb = (n + 7) / 8;  // warp-per-node grids (8 warps / 256-thread block)

    // one-time side stream + events for fork/join (host resources, created once)
    static cudaStream_t s2 = nullptr;
    static cudaEvent_t ev_fork = nullptr, ev_join = nullptr;
    if (!s2) {
        cudaStreamCreateWithFlags(&s2, cudaStreamNonBlocking);
        cudaEventCreateWithFlags(&ev_fork, cudaEventDisableTiming);
        cudaEventCreateWithFlags(&ev_join, cudaEventDisableTiming);
    }

    // fork: CSR build on s2, GEMM1 on main stream
    cudaEventRecord(ev_fork, 0);
    cudaStreamWaitEvent(s2, ev_fork, 0);

    k_detect<<<1, 256, 0, s2>>>(ei, n);
    k_deginit<<<(n + 255) / 256, 256, 0, s2>>>(n);
    k_hist<<<512, 256, 0, s2>>>(ei, E);
    k_scan1<<<nb, 256, 0, s2>>>(n);
    k_scan2<<<1, 32, 0, s2>>>(nb);
    k_scan3<<<nb, 256, 0, s2>>>(n);
    k_fill<<<832, 256, 0, s2>>>(ei, E, n);

    k_gemm1f<<<(n + 63) / 64, 256>>>(x, W1, a1s, a1d, n);

    // join
    cudaEventRecord(ev_join, s2);
    cudaStreamWaitEvent(0, ev_join, 0);

    k_maxsum1<<<wpb, 256>>>(n);
    k_gather1<<<wpb, 256>>>(b1, n);
    k_gemm2f<<<(n + 255) / 256, 256>>>(W2, a2s, a2d, n);
    k_maxsum2<<<wpb, 256>>>(n);
    k_gather2<<<wpb, 256>>>(b2, out, n);
}